// round 10
// baseline (speedup 1.0000x reference)
#include <cuda_runtime.h>
#include <math_constants.h>

#define N_SRC  4096
#define N_DST  16384
#define C_IN   256
#define C_SKIP 128
#define C_CAT  384
#define HID    512

// scratch (no dynamic alloc allowed)
__device__ float g_h[N_DST * C_CAT];       // concat(y, x_skip)  [16384,384]
__device__ float g_hidden[N_DST * HID];    // relu(h@W1+b1)      [16384,512]

#define KNN_SMEM (N_SRC * 16 + 64 * 3 * 4 + 64 * 4 * 4)

// ---------------------------------------------------------------------------
// KNN + inverse-distance interpolation + concat with x_skip.
// Arithmetic model (constrained by 7 rounds of measurements):
//   dot = fma(q2,p2, fma(q1,p1, rn(q0*p0)))        <- asc FMA    (LOCKED)
//   pp  = rn(rn(rn(p0*p0)+rn(p1*p1))+rn(p2*p2))    <- muladd asc (LOCKED)
//   qq  = rn(rn(rn(q0*q0)+rn(q2*q2))+rn(q1*q1))    <- SIMD hreduce pairing
//         (llvm pad-to-4 shuffle reduce: [a0,a1,a2,0] -> [a0+a2, a1] -> sum)
//   d2  = rn(qq + pp) - 2*dot        (Sterbenz-exact subtraction)
// 2x-in-p folding commutes bit-exactly (power-of-2).
// top_k ties -> lowest index. d2k = max(d2,1e-16); w = 1/d2k.
// ---------------------------------------------------------------------------
__global__ __launch_bounds__(256) void knn_kernel(
    const float* __restrict__ x, const float* __restrict__ pos,
    const int* __restrict__ batch,
    const float* __restrict__ x_skip, const float* __restrict__ pos_skip,
    const int* __restrict__ batch_skip, float* __restrict__ h_out)
{
    extern __shared__ char smem_raw[];
    float4* sp   = (float4*)smem_raw;                              // [N_SRC]
    int*    s_id = (int*)  (smem_raw + N_SRC * 16);                // [64*3]
    float*  s_w  = (float*)(smem_raw + N_SRC * 16 + 64 * 3 * 4);   // [64*4]

    const int tid = threadIdx.x;

    for (int j = tid; j < N_SRC; j += 256) {
        float off = (float)batch[j] * 1000.0f;  // BATCH_OFFSET (exact)
        float p0 = __fadd_rn(pos[3 * j + 0], off);
        float p1 = __fadd_rn(pos[3 * j + 1], off);
        float p2 = __fadd_rn(pos[3 * j + 2], off);
        // pp: rounded products + ASCENDING adds (LOCKED by R2's 87% match)
        float pp = __fadd_rn(__fadd_rn(__fmul_rn(p0, p0), __fmul_rn(p1, p1)),
                             __fmul_rn(p2, p2));
        sp[j] = make_float4(2.0f * p0, 2.0f * p1, 2.0f * p2, pp);
    }
    __syncthreads();

    const int dl = tid >> 2;          // 0..63 local dst
    const int s  = tid & 3;           // scan lane
    const int d  = blockIdx.x * 64 + dl;

    float off = (float)batch_skip[d] * 1000.0f;
    float q0 = __fadd_rn(pos_skip[3 * d + 0], off);
    float q1 = __fadd_rn(pos_skip[3 * d + 1], off);
    float q2 = __fadd_rn(pos_skip[3 * d + 2], off);
    // qq: (0,2)-first pairing — SIMD horizontal-reduce order (this round)
    float qq = __fadd_rn(__fadd_rn(__fmul_rn(q0, q0), __fmul_rn(q2, q2)),
                         __fmul_rn(q1, q1));

    float da = CUDART_INF_F, db = CUDART_INF_F, dc = CUDART_INF_F;
    int   ia = 0x7fffffff,  ib = 0x7fffffff,  ic = 0x7fffffff;

    #pragma unroll 2
    for (int j = s; j < N_SRC; j += 4) {
        float4 v = sp[j];
        // ascending FMA chain; x2 folded into v (exact power-of-2 commute)
        float dot2 = __fmaf_rn(q2, v.z, __fmaf_rn(q1, v.y, __fmul_rn(q0, v.x)));
        float d2   = __fsub_rn(__fadd_rn(qq, v.w), dot2);
        if (d2 < dc) {
            if (d2 < db) {
                dc = db; ic = ib;
                if (d2 < da) { db = da; ib = ia; da = d2; ia = j; }
                else         { db = d2; ib = j; }
            } else { dc = d2; ic = j; }
        }
    }

    // Merge the 4 scan lanes (lexicographic (d2, idx) for ties).
    #pragma unroll
    for (int m = 1; m <= 2; m <<= 1) {
        float oa = __shfl_xor_sync(0xffffffff, da, m);
        float ob = __shfl_xor_sync(0xffffffff, db, m);
        float oc = __shfl_xor_sync(0xffffffff, dc, m);
        int   ja = __shfl_xor_sync(0xffffffff, ia, m);
        int   jb = __shfl_xor_sync(0xffffffff, ib, m);
        int   jc = __shfl_xor_sync(0xffffffff, ic, m);
        auto ins = [&](float dv, int iv) {
            bool ltc = (dv < dc) || (dv == dc && iv < ic);
            if (ltc) {
                bool ltb = (dv < db) || (dv == db && iv < ib);
                if (ltb) {
                    dc = db; ic = ib;
                    bool lta = (dv < da) || (dv == da && iv < ia);
                    if (lta) { db = da; ib = ia; da = dv; ia = iv; }
                    else     { db = dv; ib = iv; }
                } else { dc = dv; ic = iv; }
            }
        };
        ins(oa, ja); ins(ob, jb); ins(oc, jc);
    }

    if (s == 0) {
        float w0 = __fdiv_rn(1.0f, fmaxf(da, 1e-16f));
        float w1 = __fdiv_rn(1.0f, fmaxf(db, 1e-16f));
        float w2 = __fdiv_rn(1.0f, fmaxf(dc, 1e-16f));
        s_id[dl * 3 + 0] = ia;
        s_id[dl * 3 + 1] = ib;
        s_id[dl * 3 + 2] = ic;
        s_w[dl * 4 + 0] = w0;
        s_w[dl * 4 + 1] = w1;
        s_w[dl * 4 + 2] = w2;
        s_w[dl * 4 + 3] = __fadd_rn(__fadd_rn(w0, w1), w2);
    }
    __syncthreads();

    // Cooperative gather: 256 threads = 256 channels, one dst per iteration.
    const int base = blockIdx.x * 64;
    #pragma unroll 2
    for (int t = 0; t < 64; t++) {
        int   i0 = s_id[t * 3 + 0], i1 = s_id[t * 3 + 1], i2 = s_id[t * 3 + 2];
        float w0 = s_w[t * 4 + 0],  w1 = s_w[t * 4 + 1],  w2 = s_w[t * 4 + 2];
        float sw = s_w[t * 4 + 3];
        int c = tid;
        float y0 = __fmul_rn(w0, x[i0 * C_IN + c]);
        float y1 = __fmul_rn(w1, x[i1 * C_IN + c]);
        float y2 = __fmul_rn(w2, x[i2 * C_IN + c]);
        float y  = __fadd_rn(__fadd_rn(y0, y1), y2);
        h_out[(base + t) * C_CAT + c] = __fdiv_rn(y, sw);
    }
    for (int idx = tid; idx < 64 * C_SKIP; idx += 256) {
        int t = idx >> 7, cs = idx & 127;
        h_out[(base + t) * C_CAT + C_IN + cs] =
            x_skip[(base + t) * C_SKIP + cs];
    }
}

// ---------------------------------------------------------------------------
// fp32 SGEMM: C[M,N] = A[M,K] @ B[K,N] (+bias, optional relu / residual add).
// 128x128 tile, BK=16, 256 threads, 8x8 per-thread microtile.
// ---------------------------------------------------------------------------
template <int N, int K, bool RELU, bool RESID>
__global__ __launch_bounds__(256, 2) void sgemm_kernel(
    const float* __restrict__ A, const float* __restrict__ B,
    const float* __restrict__ bias, const float* __restrict__ res,
    float* __restrict__ C)
{
    __shared__ float As[16][132];
    __shared__ float Bs[16][132];

    const int tid = threadIdx.x;
    const int m0 = blockIdx.y * 128;
    const int n0 = blockIdx.x * 128;

    const int ar = tid >> 2;          // 0..63
    const int ac = (tid & 3) * 4;     // 0,4,8,12
    const int bk = tid >> 5;          // 0..7
    const int bc = (tid & 31) * 4;    // 0..124

    const int tx = tid & 15;          // n microtile
    const int ty = tid >> 4;          // m microtile

    float acc[8][8] = {};

    for (int k0 = 0; k0 < K; k0 += 16) {
        float4 a0 = *(const float4*)&A[(m0 + ar)      * K + k0 + ac];
        float4 a1 = *(const float4*)&A[(m0 + ar + 64) * K + k0 + ac];
        float4 b0 = *(const float4*)&B[(k0 + bk)      * N + n0 + bc];
        float4 b1 = *(const float4*)&B[(k0 + bk + 8)  * N + n0 + bc];
        __syncthreads();
        As[ac + 0][ar] = a0.x; As[ac + 1][ar] = a0.y;
        As[ac + 2][ar] = a0.z; As[ac + 3][ar] = a0.w;
        As[ac + 0][ar + 64] = a1.x; As[ac + 1][ar + 64] = a1.y;
        As[ac + 2][ar + 64] = a1.z; As[ac + 3][ar + 64] = a1.w;
        *(float4*)&Bs[bk][bc]     = b0;
        *(float4*)&Bs[bk + 8][bc] = b1;
        __syncthreads();

        #pragma unroll
        for (int k = 0; k < 16; k++) {
            float4 af0 = *(const float4*)&As[k][ty * 8];
            float4 af1 = *(const float4*)&As[k][ty * 8 + 4];
            float4 bf0 = *(const float4*)&Bs[k][tx * 8];
            float4 bf1 = *(const float4*)&Bs[k][tx * 8 + 4];
            float a_[8] = {af0.x, af0.y, af0.z, af0.w, af1.x, af1.y, af1.z, af1.w};
            float b_[8] = {bf0.x, bf0.y, bf0.z, bf0.w, bf1.x, bf1.y, bf1.z, bf1.w};
            #pragma unroll
            for (int i = 0; i < 8; i++)
                #pragma unroll
                for (int j = 0; j < 8; j++)
                    acc[i][j] = __fmaf_rn(a_[i], b_[j], acc[i][j]);
        }
    }

    #pragma unroll
    for (int i = 0; i < 8; i++) {
        const int gm = m0 + ty * 8 + i;
        #pragma unroll
        for (int j = 0; j < 8; j++) {
            const int gn = n0 + tx * 8 + j;
            float v = acc[i][j] + bias[gn];
            if (RELU)  v = fmaxf(v, 0.0f);
            if (RESID) v += res[gm * N + gn];
            C[gm * N + gn] = v;
        }
    }
}

// ---------------------------------------------------------------------------
// Tail outputs: pos_skip (f32) and batch_skip (i32) appended after out.
// ---------------------------------------------------------------------------
__global__ void tail_kernel(const float* __restrict__ pos_skip,
                            const int* __restrict__ batch_skip,
                            float* __restrict__ out, int write_batch)
{
    int i = blockIdx.x * 256 + threadIdx.x;
    if (i < N_DST * 3) out[N_DST * C_CAT + i] = pos_skip[i];
    if (write_batch && i < N_DST)
        out[N_DST * C_CAT + N_DST * 3 + i] = (float)batch_skip[i];
}

extern "C" void kernel_launch(void* const* d_in, const int* in_sizes, int n_in,
                              void* d_out, int out_size)
{
    const float* x          = (const float*)d_in[0];
    const float* pos        = (const float*)d_in[1];
    const int*   batch      = (const int*)d_in[2];
    const float* x_skip     = (const float*)d_in[3];
    const float* pos_skip   = (const float*)d_in[4];
    const int*   batch_skip = (const int*)d_in[5];
    const float* W1         = (const float*)d_in[6];
    const float* b1         = (const float*)d_in[7];
    const float* W2         = (const float*)d_in[8];
    const float* b2         = (const float*)d_in[9];
    float* out = (float*)d_out;

    float *hbuf, *hidbuf;
    cudaGetSymbolAddress((void**)&hbuf, g_h);
    cudaGetSymbolAddress((void**)&hidbuf, g_hidden);

    cudaFuncSetAttribute(knn_kernel,
                         cudaFuncAttributeMaxDynamicSharedMemorySize, KNN_SMEM);

    knn_kernel<<<N_DST / 64, 256, KNN_SMEM>>>(x, pos, batch, x_skip, pos_skip,
                                              batch_skip, hbuf);

    sgemm_kernel<HID, C_CAT, true, false>
        <<<dim3(HID / 128, N_DST / 128), 256>>>(hbuf, W1, b1, nullptr, hidbuf);

    sgemm_kernel<C_CAT, HID, false, true>
        <<<dim3(C_CAT / 128, N_DST / 128), 256>>>(hidbuf, W2, b2, hbuf, out);

    if (out_size >= N_DST * C_CAT + N_DST * 3) {
        int wb = (out_size >= N_DST * C_CAT + N_DST * 3 + N_DST) ? 1 : 0;
        tail_kernel<<<(N_DST * 3 + 255) / 256, 256>>>(pos_skip, batch_skip,
                                                      out, wb);
    }
}

// round 12
// speedup vs baseline: 1.7453x; 1.7453x over previous
#include <cuda_runtime.h>
#include <cuda_bf16.h>
#include <math_constants.h>
#include <mma.h>
#include <cstdint>

using namespace nvcuda;

#define N_SRC  4096
#define N_DST  16384
#define C_IN   256
#define C_SKIP 128
#define C_CAT  384
#define HID    512

// scratch (no dynamic alloc allowed)
__device__ float          g_h [N_DST * C_CAT];   // concat(y,x_skip) fp32 (residual)
__device__ __nv_bfloat16  g_hh[N_DST * C_CAT];   // h hi
__device__ __nv_bfloat16  g_hl[N_DST * C_CAT];   // h lo
__device__ __nv_bfloat16  g_dh[N_DST * HID];     // hidden hi
__device__ __nv_bfloat16  g_dl[N_DST * HID];     // hidden lo
__device__ __nv_bfloat16  g_w1h[HID * C_CAT];    // W1^T hi  [512][384]
__device__ __nv_bfloat16  g_w1l[HID * C_CAT];
__device__ __nv_bfloat16  g_w2h[C_CAT * HID];    // W2^T hi  [384][512]
__device__ __nv_bfloat16  g_w2l[C_CAT * HID];

#define KNN_SMEM (N_SRC * 16 + 64 * 3 * 4 + 64 * 4 * 4)

// ======================== KNN (arithmetic LOCKED, passes 1.3e-7) ============
__global__ __launch_bounds__(256) void knn_kernel(
    const float* __restrict__ x, const float* __restrict__ pos,
    const int* __restrict__ batch,
    const float* __restrict__ x_skip, const float* __restrict__ pos_skip,
    const int* __restrict__ batch_skip, float* __restrict__ h_out,
    __nv_bfloat16* __restrict__ hh_out, __nv_bfloat16* __restrict__ hl_out)
{
    extern __shared__ char smem_raw[];
    float4* sp   = (float4*)smem_raw;
    int*    s_id = (int*)  (smem_raw + N_SRC * 16);
    float*  s_w  = (float*)(smem_raw + N_SRC * 16 + 64 * 3 * 4);

    const int tid = threadIdx.x;

    for (int j = tid; j < N_SRC; j += 256) {
        float off = (float)batch[j] * 1000.0f;
        float p0 = __fadd_rn(pos[3 * j + 0], off);
        float p1 = __fadd_rn(pos[3 * j + 1], off);
        float p2 = __fadd_rn(pos[3 * j + 2], off);
        float pp = __fadd_rn(__fadd_rn(__fmul_rn(p0, p0), __fmul_rn(p1, p1)),
                             __fmul_rn(p2, p2));
        sp[j] = make_float4(2.0f * p0, 2.0f * p1, 2.0f * p2, pp);
    }
    __syncthreads();

    const int dl = tid >> 2;
    const int s  = tid & 3;
    const int d  = blockIdx.x * 64 + dl;

    float off = (float)batch_skip[d] * 1000.0f;
    float q0 = __fadd_rn(pos_skip[3 * d + 0], off);
    float q1 = __fadd_rn(pos_skip[3 * d + 1], off);
    float q2 = __fadd_rn(pos_skip[3 * d + 2], off);
    // qq: (0,2)-first SIMD hreduce pairing (LOCKED)
    float qq = __fadd_rn(__fadd_rn(__fmul_rn(q0, q0), __fmul_rn(q2, q2)),
                         __fmul_rn(q1, q1));

    float da = CUDART_INF_F, db = CUDART_INF_F, dc = CUDART_INF_F;
    int   ia = 0x7fffffff,  ib = 0x7fffffff,  ic = 0x7fffffff;

    #pragma unroll 2
    for (int j = s; j < N_SRC; j += 4) {
        float4 v = sp[j];
        float dot2 = __fmaf_rn(q2, v.z, __fmaf_rn(q1, v.y, __fmul_rn(q0, v.x)));
        float d2   = __fsub_rn(__fadd_rn(qq, v.w), dot2);
        if (d2 < dc) {
            if (d2 < db) {
                dc = db; ic = ib;
                if (d2 < da) { db = da; ib = ia; da = d2; ia = j; }
                else         { db = d2; ib = j; }
            } else { dc = d2; ic = j; }
        }
    }

    #pragma unroll
    for (int m = 1; m <= 2; m <<= 1) {
        float oa = __shfl_xor_sync(0xffffffff, da, m);
        float ob = __shfl_xor_sync(0xffffffff, db, m);
        float oc = __shfl_xor_sync(0xffffffff, dc, m);
        int   ja = __shfl_xor_sync(0xffffffff, ia, m);
        int   jb = __shfl_xor_sync(0xffffffff, ib, m);
        int   jc = __shfl_xor_sync(0xffffffff, ic, m);
        auto ins = [&](float dv, int iv) {
            bool ltc = (dv < dc) || (dv == dc && iv < ic);
            if (ltc) {
                bool ltb = (dv < db) || (dv == db && iv < ib);
                if (ltb) {
                    dc = db; ic = ib;
                    bool lta = (dv < da) || (dv == da && iv < ia);
                    if (lta) { db = da; ib = ia; da = dv; ia = iv; }
                    else     { db = dv; ib = iv; }
                } else { dc = dv; ic = iv; }
            }
        };
        ins(oa, ja); ins(ob, jb); ins(oc, jc);
    }

    if (s == 0) {
        float w0 = __fdiv_rn(1.0f, fmaxf(da, 1e-16f));
        float w1 = __fdiv_rn(1.0f, fmaxf(db, 1e-16f));
        float w2 = __fdiv_rn(1.0f, fmaxf(dc, 1e-16f));
        s_id[dl * 3 + 0] = ia; s_id[dl * 3 + 1] = ib; s_id[dl * 3 + 2] = ic;
        s_w[dl * 4 + 0] = w0; s_w[dl * 4 + 1] = w1; s_w[dl * 4 + 2] = w2;
        s_w[dl * 4 + 3] = __fadd_rn(__fadd_rn(w0, w1), w2);
    }
    __syncthreads();

    const int base = blockIdx.x * 64;
    #pragma unroll 2
    for (int t = 0; t < 64; t++) {
        int   i0 = s_id[t * 3 + 0], i1 = s_id[t * 3 + 1], i2 = s_id[t * 3 + 2];
        float w0 = s_w[t * 4 + 0],  w1 = s_w[t * 4 + 1],  w2 = s_w[t * 4 + 2];
        float sw = s_w[t * 4 + 3];
        int c = tid;
        float y0 = __fmul_rn(w0, x[i0 * C_IN + c]);
        float y1 = __fmul_rn(w1, x[i1 * C_IN + c]);
        float y2 = __fmul_rn(w2, x[i2 * C_IN + c]);
        float y  = __fadd_rn(__fadd_rn(y0, y1), y2);
        float val = __fdiv_rn(y, sw);
        size_t o = (size_t)(base + t) * C_CAT + c;
        h_out[o] = val;
        __nv_bfloat16 vh = __float2bfloat16(val);
        hh_out[o] = vh;
        hl_out[o] = __float2bfloat16(val - __bfloat162float(vh));
    }
    for (int idx = tid; idx < 64 * C_SKIP; idx += 256) {
        int t = idx >> 7, cs = idx & 127;
        float val = x_skip[(base + t) * C_SKIP + cs];
        size_t o = (size_t)(base + t) * C_CAT + C_IN + cs;
        h_out[o] = val;
        __nv_bfloat16 vh = __float2bfloat16(val);
        hh_out[o] = vh;
        hl_out[o] = __float2bfloat16(val - __bfloat162float(vh));
    }
}

// ============== weight transpose + bf16 split (tiny prep) ===================
__global__ void convw_kernel(const float* __restrict__ W1,
                             const float* __restrict__ W2,
                             __nv_bfloat16* __restrict__ w1h,
                             __nv_bfloat16* __restrict__ w1l,
                             __nv_bfloat16* __restrict__ w2h,
                             __nv_bfloat16* __restrict__ w2l)
{
    int i = blockIdx.x * 256 + threadIdx.x;
    if (i < C_CAT * HID) {             // W1 [384,512] -> w1t [512,384]
        float v = W1[i];
        int k = i / HID, n = i % HID;
        __nv_bfloat16 h = __float2bfloat16(v);
        w1h[n * C_CAT + k] = h;
        w1l[n * C_CAT + k] = __float2bfloat16(v - __bfloat162float(h));
    }
    if (i < HID * C_CAT) {             // W2 [512,384] -> w2t [384,512]
        float v = W2[i];
        int k = i / C_CAT, n = i % C_CAT;
        __nv_bfloat16 h = __float2bfloat16(v);
        w2h[n * HID + k] = h;
        w2l[n * HID + k] = __float2bfloat16(v - __bfloat162float(h));
    }
}

// =================== WMMA bf16-split GEMM (legacy HMMA path) ================
// C[M,N] = (Ah+Al)[M,K] @ (Bh+Bl)^T[N,K], fp32 accum, 3 bf16 MMAs per tile.
// CTA 128x128, 8 warps (4M x 2N), warp tile 32x64 (2x4 wmma m16n16k16).
// K chunks of 64 in smem (stride 72 halves); epilogue staged through smem.
#define LDS 72                          // smem row stride in halves
#define TILE_H (128 * LDS)              // halves per operand tile
#define G_SMEM (4 * TILE_H * 2)         // 73728 bytes

template <int KT, int NT, bool RELU, bool SPLIT>
__global__ __launch_bounds__(256, 2) void gemm_kernel(
    const __nv_bfloat16* __restrict__ Ah, const __nv_bfloat16* __restrict__ Al,
    const __nv_bfloat16* __restrict__ Bh, const __nv_bfloat16* __restrict__ Bl,
    const float* __restrict__ bias, const float* __restrict__ res,
    __nv_bfloat16* __restrict__ Oh, __nv_bfloat16* __restrict__ Ol,
    float* __restrict__ Of)
{
    extern __shared__ char smem[];
    __nv_bfloat16* sAh = (__nv_bfloat16*)smem;
    __nv_bfloat16* sAl = sAh + TILE_H;
    __nv_bfloat16* sBh = sAl + TILE_H;
    __nv_bfloat16* sBl = sBh + TILE_H;

    const int tid = threadIdx.x;
    const int wid = tid >> 5;
    const int n0 = blockIdx.x * 128;
    const int m0 = blockIdx.y * 128;
    const int wm = (wid & 3) * 32;      // warp M offset in tile
    const int wn = (wid >> 2) * 64;     // warp N offset in tile

    wmma::fragment<wmma::accumulator, 16, 16, 16, float> acc[2][4];
    #pragma unroll
    for (int i = 0; i < 2; i++)
        #pragma unroll
        for (int j = 0; j < 4; j++)
            wmma::fill_fragment(acc[i][j], 0.0f);

    constexpr int NCHUNK = KT / 64;
    for (int c = 0; c < NCHUNK; c++) {
        const int k0 = c * 64;
        {
            const __nv_bfloat16* srcs[4] = {
                Ah + (size_t)m0 * KT + k0, Al + (size_t)m0 * KT + k0,
                Bh + (size_t)n0 * KT + k0, Bl + (size_t)n0 * KT + k0 };
            __nv_bfloat16* dsts[4] = {sAh, sAl, sBh, sBl};
            #pragma unroll
            for (int t = 0; t < 4; t++) {
                const char* sp = (const char*)srcs[t];
                char* dp = (char*)dsts[t];
                #pragma unroll
                for (int i = tid; i < 1024; i += 256) {
                    int r = i >> 3, j = i & 7;       // row 0..127, 16B piece
                    uint4 v = *(const uint4*)(sp + (size_t)r * (KT * 2) + j * 16);
                    *(uint4*)(dp + r * (LDS * 2) + j * 16) = v;
                }
            }
        }
        __syncthreads();

        #pragma unroll
        for (int ks = 0; ks < 4; ks++) {
            const int kk = ks * 16;
            wmma::fragment<wmma::matrix_a, 16, 16, 16, __nv_bfloat16,
                           wmma::row_major> a_h[2], a_l[2];
            #pragma unroll
            for (int i = 0; i < 2; i++) {
                wmma::load_matrix_sync(a_h[i], sAh + (wm + i * 16) * LDS + kk, LDS);
                wmma::load_matrix_sync(a_l[i], sAl + (wm + i * 16) * LDS + kk, LDS);
            }
            #pragma unroll
            for (int j = 0; j < 4; j++) {
                wmma::fragment<wmma::matrix_b, 16, 16, 16, __nv_bfloat16,
                               wmma::col_major> b_h, b_l;
                // memory [n][k] row-major == (K x N) col-major with ld=LDS
                wmma::load_matrix_sync(b_h, sBh + (wn + j * 16) * LDS + kk, LDS);
                wmma::load_matrix_sync(b_l, sBl + (wn + j * 16) * LDS + kk, LDS);
                #pragma unroll
                for (int i = 0; i < 2; i++) {
                    wmma::mma_sync(acc[i][j], a_h[i], b_h, acc[i][j]);
                    wmma::mma_sync(acc[i][j], a_h[i], b_l, acc[i][j]);
                    wmma::mma_sync(acc[i][j], a_l[i], b_h, acc[i][j]);
                }
            }
        }
        __syncthreads();
    }

    // epilogue: stage fp32 tile through smem (reuse operand space, 64KB)
    float* sC = (float*)smem;
    #pragma unroll
    for (int i = 0; i < 2; i++)
        #pragma unroll
        for (int j = 0; j < 4; j++)
            wmma::store_matrix_sync(sC + (wm + i * 16) * 128 + wn + j * 16,
                                    acc[i][j], 128, wmma::mem_row_major);
    __syncthreads();

    for (int idx = tid; idx < 128 * 128; idx += 256) {
        const int r = idx >> 7, cc = idx & 127;
        const int m = m0 + r, n = n0 + cc;
        float v = sC[idx] + bias[n];
        if (RELU) v = fmaxf(v, 0.0f);
        if (SPLIT) {
            __nv_bfloat16 vh = __float2bfloat16(v);
            Oh[(size_t)m * NT + n] = vh;
            Ol[(size_t)m * NT + n] = __float2bfloat16(v - __bfloat162float(vh));
        } else {
            Of[(size_t)m * NT + n] = v + res[(size_t)m * NT + n];
        }
    }
}

// ======================== tail outputs ======================================
__global__ void tail_kernel(const float* __restrict__ pos_skip,
                            const int* __restrict__ batch_skip,
                            float* __restrict__ out, int write_batch)
{
    int i = blockIdx.x * 256 + threadIdx.x;
    if (i < N_DST * 3) out[N_DST * C_CAT + i] = pos_skip[i];
    if (write_batch && i < N_DST)
        out[N_DST * C_CAT + N_DST * 3 + i] = (float)batch_skip[i];
}

extern "C" void kernel_launch(void* const* d_in, const int* in_sizes, int n_in,
                              void* d_out, int out_size)
{
    const float* x          = (const float*)d_in[0];
    const float* pos        = (const float*)d_in[1];
    const int*   batch      = (const int*)d_in[2];
    const float* x_skip     = (const float*)d_in[3];
    const float* pos_skip   = (const float*)d_in[4];
    const int*   batch_skip = (const int*)d_in[5];
    const float* W1         = (const float*)d_in[6];
    const float* b1         = (const float*)d_in[7];
    const float* W2         = (const float*)d_in[8];
    const float* b2         = (const float*)d_in[9];
    float* out = (float*)d_out;

    float *hbuf; __nv_bfloat16 *hh, *hl, *dh, *dl, *w1h, *w1l, *w2h, *w2l;
    cudaGetSymbolAddress((void**)&hbuf, g_h);
    cudaGetSymbolAddress((void**)&hh, g_hh);
    cudaGetSymbolAddress((void**)&hl, g_hl);
    cudaGetSymbolAddress((void**)&dh, g_dh);
    cudaGetSymbolAddress((void**)&dl, g_dl);
    cudaGetSymbolAddress((void**)&w1h, g_w1h);
    cudaGetSymbolAddress((void**)&w1l, g_w1l);
    cudaGetSymbolAddress((void**)&w2h, g_w2h);
    cudaGetSymbolAddress((void**)&w2l, g_w2l);

    cudaFuncSetAttribute(knn_kernel,
                         cudaFuncAttributeMaxDynamicSharedMemorySize, KNN_SMEM);
    cudaFuncSetAttribute(gemm_kernel<C_CAT, HID, true, true>,
                         cudaFuncAttributeMaxDynamicSharedMemorySize, G_SMEM);
    cudaFuncSetAttribute(gemm_kernel<HID, C_CAT, false, false>,
                         cudaFuncAttributeMaxDynamicSharedMemorySize, G_SMEM);

    knn_kernel<<<N_DST / 64, 256, KNN_SMEM>>>(x, pos, batch, x_skip, pos_skip,
                                              batch_skip, hbuf, hh, hl);

    convw_kernel<<<(C_CAT * HID + 255) / 256, 256>>>(W1, W2, w1h, w1l,
                                                     w2h, w2l);

    // hidden = relu(h @ W1 + b1)  -> bf16 split
    gemm_kernel<C_CAT, HID, true, true>
        <<<dim3(HID / 128, N_DST / 128), 256, G_SMEM>>>(
            hh, hl, w1h, w1l, b1, nullptr, dh, dl, nullptr);

    // out = hidden @ W2 + b2 + h
    gemm_kernel<HID, C_CAT, false, false>
        <<<dim3(C_CAT / 128, N_DST / 128), 256, G_SMEM>>>(
            dh, dl, w2h, w2l, b2, hbuf, nullptr, nullptr, out);

    if (out_size >= N_DST * C_CAT + N_DST * 3) {
        int wb = (out_size >= N_DST * C_CAT + N_DST * 3 + N_DST) ? 1 : 0;
        tail_kernel<<<(N_DST * 3 + 255) / 256, 256>>>(pos_skip, batch_skip,
                                                      out, wb);
    }
}